// round 12
// baseline (speedup 1.0000x reference)
#include <cuda_runtime.h>
#include <cuda_bf16.h>
#include <math.h>
#include <stdint.h>

// Problem constants
#define NN   50000
#define EE   800000
#define FDIM 128
#define HDIM 64
#define LL   3
#define GG   256
#define CC   10
#define TCOLS 384   // 3 n-blocks of 128: [W2(hom|het) | W1(hom|het) | W0(hom|het)]

// ---------------- scratch (__device__ globals; no allocation allowed) ----------------
__device__ float g_T[(size_t)NN * TCOLS];     // per-layer GEMM output [N,384]
__device__ float g_h[(size_t)NN * FDIM];      // node features [N,128] (hom|het)
__device__ float g_u[(size_t)NN * FDIM];      // hop scratch [N,128] (hom|het)
// pre-split bf16 B images: [L][3 nblocks][2 planes][n=128][k=64 words]  (32KB per plane)
__device__ unsigned g_Wbf[LL * 3 * 2 * 8192];

__device__ int    g_cnt[NN];
__device__ int    g_fill[NN];
__device__ int    g_rowptr[NN + 1];
__device__ int    g_blk[256];
__device__ int    g_blkoff[256];
__device__ float4 g_edge[EE];                 // (src_as_int_bits, hom, het, unused)
__device__ float  g_deg_hom[NN];
__device__ float  g_deg_het[NN];
__device__ int    g_gptr[GG + 1];
__device__ float  g_r[GG * 4 * HDIM];         // readout accumulator [G,256]

// ---------------- CSR build ----------------
__global__ void init_zero_kernel() {
    int i = blockIdx.x * blockDim.x + threadIdx.x;
    if (i < NN) {
        g_cnt[i] = 0;
        g_deg_hom[i] = 0.f;
        g_deg_het[i] = 0.f;
    }
}

__global__ void count_kernel(const int* __restrict__ ei,
                             const float* __restrict__ hm,
                             const float* __restrict__ tm) {
    int e = blockIdx.x * blockDim.x + threadIdx.x;
    if (e >= EE) return;
    int d = ei[EE + e];             // dst row of edge_index
    atomicAdd(&g_cnt[d], 1);
    atomicAdd(&g_deg_hom[d], hm[e]);
    atomicAdd(&g_deg_het[d], tm[e]);
}

// parallel exclusive scan of g_cnt -> g_rowptr/g_fill (3 kernels)
__global__ void blkscan_kernel() {   // grid 196, block 256
    __shared__ int s[256];
    int t = threadIdx.x;
    int i = blockIdx.x * 256 + t;
    int v = (i < NN) ? g_cnt[i] : 0;
    s[t] = v;
    __syncthreads();
#pragma unroll
    for (int off = 1; off < 256; off <<= 1) {
        int x = (t >= off) ? s[t - off] : 0;
        __syncthreads();
        s[t] += x;
        __syncthreads();
    }
    if (i < NN) g_rowptr[i] = s[t] - v;      // exclusive within block
    if (t == 255) g_blk[blockIdx.x] = s[255];
}

__global__ void blkoff_kernel(int nblk) {    // 1 block 256
    __shared__ int s[256];
    int t = threadIdx.x;
    int v = (t < nblk) ? g_blk[t] : 0;
    s[t] = v;
    __syncthreads();
#pragma unroll
    for (int off = 1; off < 256; off <<= 1) {
        int x = (t >= off) ? s[t - off] : 0;
        __syncthreads();
        s[t] += x;
        __syncthreads();
    }
    g_blkoff[t] = s[t] - v;                  // exclusive
}

__global__ void finalize_scan_kernel() {     // grid 196, block 256
    int i = blockIdx.x * blockDim.x + threadIdx.x;
    if (i < NN) {
        int r = g_rowptr[i] + g_blkoff[i >> 8];
        g_rowptr[i] = r;
        g_fill[i] = r;
    }
    if (i == 0) g_rowptr[NN] = EE;
}

__global__ void scatter_kernel(const int* __restrict__ ei,
                               const float* __restrict__ hm,
                               const float* __restrict__ tm) {
    int e = blockIdx.x * blockDim.x + threadIdx.x;
    if (e >= EE) return;
    int d = ei[EE + e];
    int p = atomicAdd(&g_fill[d], 1);
    float4 rec;
    rec.x = __int_as_float(ei[e]);
    rec.y = hm[e];
    rec.z = tm[e];
    rec.w = 0.f;
    g_edge[p] = rec;
}

__global__ void gptr_kernel(const int* __restrict__ batch) {
    int n = blockIdx.x * blockDim.x + threadIdx.x;
    if (n >= NN) return;
    int b = batch[n];
    int prev = (n == 0) ? -1 : batch[n - 1];
    for (int g = prev + 1; g <= b; ++g) g_gptr[g] = n;
    if (n == NN - 1) {
        for (int g = b + 1; g <= GG; ++g) g_gptr[g] = NN;
    }
}

// ---------------- bf16 split ----------------
__device__ __forceinline__ void bf_split(float x, unsigned short& h, unsigned short& l) {
    __nv_bfloat16 hb = __float2bfloat16(x);
    float hf = __bfloat162float(hb);
    __nv_bfloat16 lb = __float2bfloat16(x - hf);
    h = __bfloat16_as_ushort(hb);
    l = __bfloat16_as_ushort(lb);
}

// pack all layers' weights: B[n][k] = W_l[hop j][k][col], split hi/lo planes.
// n-block t covers T cols t*128..t*128+127 -> hop j = 2 - t; view = (n>=64)
__global__ void packWbf_kernel(const float* __restrict__ homW,
                               const float* __restrict__ hetW) {
    int idx = blockIdx.x * blockDim.x + threadIdx.x;
    if (idx >= LL * 3 * 128 * 64) return;
    int kp = idx & 63;
    int n = (idx >> 6) & 127;
    int t = (idx >> 13) % 3;
    int l = idx / (3 * 128 * 64);
    int j = 2 - t;
    int v = (n >> 6) & 1;
    int cc = n & 63;
    const float* Ws = v ? hetW : homW;
    int k0 = 2 * kp;
    float f0 = Ws[((size_t)(l * 3 + j) * FDIM + k0) * HDIM + cc];
    float f1 = Ws[((size_t)(l * 3 + j) * FDIM + k0 + 1) * HDIM + cc];
    unsigned short h0, l0, h1, l1;
    bf_split(f0, h0, l0);
    bf_split(f1, h1, l1);
    unsigned* baseH = &g_Wbf[((size_t)(l * 3 + t) * 2 + 0) * 8192];
    unsigned* baseL = &g_Wbf[((size_t)(l * 3 + t) * 2 + 1) * 8192];
    baseH[n * 64 + kp] = (unsigned)h0 | ((unsigned)h1 << 16);
    baseL[n * 64 + kp] = (unsigned)l0 | ((unsigned)l1 << 16);
}

// ---------------- 3-pass bf16 mma.sync GEMM (v5): cp.async pipelined ----------------
#define MTILE 64
#define WPAD 68                            // words per row (stride 4 banks -> conflict-free)
#define SM_AHI 0
#define SM_ALO (MTILE * WPAD)              // 4352
#define SM_B   (2 * MTILE * WPAD)          // 8704
#define BUFW   (2 * 64 * WPAD)             // 8704 words per B buffer (2 planes x 64 rows)
#define SM_WORDS (SM_B + 2 * BUFW)         // 26112 words = 104448 B

#define MMA_BF16(d, a0, a1, a2, a3, b0, b1)                                     \
    asm volatile(                                                               \
        "mma.sync.aligned.m16n8k16.row.col.f32.bf16.bf16.f32 "                  \
        "{%0,%1,%2,%3}, {%4,%5,%6,%7}, {%8,%9}, {%0,%1,%2,%3};"                 \
        : "+f"(d[0]), "+f"(d[1]), "+f"(d[2]), "+f"(d[3])                        \
        : "r"(a0), "r"(a1), "r"(a2), "r"(a3), "r"(b0), "r"(b1));

#define CP_ASYNC16(dst_u32, src_ptr)                                            \
    asm volatile("cp.async.cg.shared.global [%0], [%1], 16;"                    \
                 :: "r"(dst_u32), "l"(src_ptr) : "memory")
#define CP_COMMIT() asm volatile("cp.async.commit_group;" ::: "memory")
#define CP_WAIT1()  asm volatile("cp.async.wait_group 1;" ::: "memory")

__device__ __forceinline__ uint32_t smem_u32(const void* p) {
    uint32_t a;
    asm("{ .reg .u64 t; cvta.to.shared.u64 t, %1; cvt.u32.u64 %0, t; }" : "=r"(a) : "l"(p));
    return a;
}
__device__ __forceinline__ void ldsm_x4(unsigned& r0, unsigned& r1, unsigned& r2, unsigned& r3,
                                        uint32_t addr) {
    asm volatile("ldmatrix.sync.aligned.m8n8.x4.shared.b16 {%0,%1,%2,%3}, [%4];"
                 : "=r"(r0), "=r"(r1), "=r"(r2), "=r"(r3) : "r"(addr));
}

__global__ __launch_bounds__(256, 2) void gemm_bf16_kernel(const float* __restrict__ A,
                                                           const unsigned* __restrict__ Wb,
                                                           float* __restrict__ C) {
    extern __shared__ unsigned sm[];
    const uint32_t sbase = smem_u32(sm);
    const int tid = threadIdx.x;
    const int lane = tid & 31;
    const int wid = tid >> 5;
    const int g = lane >> 2;
    const int tg = lane & 3;
    const int warpRow = (wid & 1) * 32;        // 2 m-warps
    const int warpCol = (wid >> 1) * 16;       // 4 n-warps x 16 cols (within 64-col chunk)
    const int mBase = blockIdx.x * MTILE;

    auto prefetch = [&](int c) {
        int t = c >> 1, half = c & 1, buf = c & 1;
#pragma unroll
        for (int j = 0; j < 8; j++) {
            int task = tid + j * 256;              // 0..2047
            int plane = task >> 10;                // 0..1
            int rem = task & 1023;
            int r = rem >> 4;                      // 0..63
            int q = rem & 15;                      // 16B unit within row
            uint32_t dstw = SM_B + buf * BUFW + plane * (64 * WPAD) + r * WPAD + q * 4;
            const unsigned* src = Wb + (size_t)(t * 2 + plane) * 8192 + (half * 64 + r) * 64 + q * 4;
            CP_ASYNC16(sbase + dstw * 4, src);
        }
    };

    prefetch(0);
    CP_COMMIT();
    prefetch(1);
    CP_COMMIT();

    // ---- convert A tile [64 x 128] f32 -> bf16 hi/lo planes (overlaps prefetch) ----
    for (int it = tid; it < MTILE * 32; it += 256) {
        int row = it >> 5;
        int c4 = it & 31;
        int grow = mBase + row;
        float4 v = make_float4(0.f, 0.f, 0.f, 0.f);
        if (grow < NN) v = *(const float4*)&A[(size_t)grow * FDIM + 4 * c4];
        unsigned short hx, lx, hy, ly, hz, lz, hw, lw;
        bf_split(v.x, hx, lx);
        bf_split(v.y, hy, ly);
        bf_split(v.z, hz, lz);
        bf_split(v.w, hw, lw);
        int w0 = row * WPAD + 2 * c4;
        sm[SM_AHI + w0]     = (unsigned)hx | ((unsigned)hy << 16);
        sm[SM_AHI + w0 + 1] = (unsigned)hz | ((unsigned)hw << 16);
        sm[SM_ALO + w0]     = (unsigned)lx | ((unsigned)ly << 16);
        sm[SM_ALO + w0 + 1] = (unsigned)lz | ((unsigned)lw << 16);
    }

    const int aRow = (lane & 7) + ((lane >> 3) & 1) * 8;
    const int aWordSel = ((lane >> 4) & 1) * 4;
    const int bRowIdx = ((lane >> 4) & 1) * 8 + (lane & 7);
    const int bWordSel = ((lane >> 3) & 1) * 4;

    for (int c = 0; c < 6; c++) {
        const int t = c >> 1, half = c & 1, buf = c & 1;
        CP_WAIT1();
        __syncthreads();

        float acc[2][2][4];
#pragma unroll
        for (int mi = 0; mi < 2; mi++)
#pragma unroll
            for (int ni = 0; ni < 2; ni++)
#pragma unroll
                for (int r = 0; r < 4; r++) acc[mi][ni][r] = 0.f;

        const uint32_t bH = sbase + (SM_B + buf * BUFW) * 4;
        const uint32_t bL = bH + (64 * WPAD) * 4;

#pragma unroll
        for (int ks = 0; ks < 8; ks++) {
            unsigned ah[2][4], al[2][4];
#pragma unroll
            for (int mi = 0; mi < 2; mi++) {
                uint32_t off = (uint32_t)((warpRow + mi * 16 + aRow) * WPAD + 8 * ks + aWordSel) * 4;
                ldsm_x4(ah[mi][0], ah[mi][1], ah[mi][2], ah[mi][3],
                        sbase + SM_AHI * 4 + off);
                ldsm_x4(al[mi][0], al[mi][1], al[mi][2], al[mi][3],
                        sbase + SM_ALO * 4 + off);
            }
            unsigned bh[2][2], bl[2][2];
            {
                uint32_t off = (uint32_t)((warpCol + bRowIdx) * WPAD + 8 * ks + bWordSel) * 4;
                ldsm_x4(bh[0][0], bh[0][1], bh[1][0], bh[1][1], bH + off);
                ldsm_x4(bl[0][0], bl[0][1], bl[1][0], bl[1][1], bL + off);
            }
#pragma unroll
            for (int ni = 0; ni < 2; ni++)
#pragma unroll
                for (int mi = 0; mi < 2; mi++)
                    MMA_BF16(acc[mi][ni], ah[mi][0], ah[mi][1], ah[mi][2], ah[mi][3],
                             bh[ni][0], bh[ni][1]);
#pragma unroll
            for (int ni = 0; ni < 2; ni++)
#pragma unroll
                for (int mi = 0; mi < 2; mi++)
                    MMA_BF16(acc[mi][ni], al[mi][0], al[mi][1], al[mi][2], al[mi][3],
                             bh[ni][0], bh[ni][1]);
#pragma unroll
            for (int ni = 0; ni < 2; ni++)
#pragma unroll
                for (int mi = 0; mi < 2; mi++)
                    MMA_BF16(acc[mi][ni], ah[mi][0], ah[mi][1], ah[mi][2], ah[mi][3],
                             bl[ni][0], bl[ni][1]);
        }

#pragma unroll
        for (int mi = 0; mi < 2; mi++) {
            int gr0 = mBase + warpRow + mi * 16 + g;
            int gr1 = gr0 + 8;
#pragma unroll
            for (int ni = 0; ni < 2; ni++) {
                int gc = t * 128 + half * 64 + warpCol + ni * 8 + 2 * tg;
                if (gr0 < NN)
                    *(float2*)&C[(size_t)gr0 * TCOLS + gc] = make_float2(acc[mi][ni][0], acc[mi][ni][1]);
                if (gr1 < NN)
                    *(float2*)&C[(size_t)gr1 * TCOLS + gc] = make_float2(acc[mi][ni][2], acc[mi][ni][3]);
            }
        }
        __syncthreads();
        if (c + 2 < 6) prefetch(c + 2);
        CP_COMMIT();
    }
}

// ---------------- fused two-view aggregation (v2): packed edges + 2-wide pipeline ----------------
__global__ void agg2_kernel(const float* __restrict__ gather, int gld,
                            const float* __restrict__ add, int ald, int acol,
                            const float* __restrict__ hom_b,  // non-null => relu(.+bias)
                            const float* __restrict__ het_b,
                            float* __restrict__ out) {
    int gw = (blockIdx.x * blockDim.x + threadIdx.x) >> 5;
    int lane = threadIdx.x & 31;
    if (gw >= NN) return;
    const bool het = lane >= 16;
    const int s = g_rowptr[gw];
    const int e = g_rowptr[gw + 1];

    // hoisted independent loads (overlap with edge loop)
    float d = fmaxf(het ? g_deg_het[gw] : g_deg_hom[gw], 1.f);
    float4 a = *(const float4*)&add[(size_t)gw * ald + acol + 4 * lane];

    float ax = 0.f, ay = 0.f, az = 0.f, aw = 0.f;
    float bx = 0.f, by = 0.f, bz = 0.f, bw = 0.f;
    int i = s;
    for (; i + 2 <= e; i += 2) {
        float4 e0 = g_edge[i];
        float4 e1 = g_edge[i + 1];
        int sr0 = __float_as_int(e0.x);
        int sr1 = __float_as_int(e1.x);
        float m0 = het ? e0.z : e0.y;
        float m1 = het ? e1.z : e1.y;
        float4 v0 = *(const float4*)&gather[(size_t)sr0 * gld + 4 * lane];
        float4 v1 = *(const float4*)&gather[(size_t)sr1 * gld + 4 * lane];
        ax = fmaf(m0, v0.x, ax);
        ay = fmaf(m0, v0.y, ay);
        az = fmaf(m0, v0.z, az);
        aw = fmaf(m0, v0.w, aw);
        bx = fmaf(m1, v1.x, bx);
        by = fmaf(m1, v1.y, by);
        bz = fmaf(m1, v1.z, bz);
        bw = fmaf(m1, v1.w, bw);
    }
    if (i < e) {
        float4 e0 = g_edge[i];
        int sr0 = __float_as_int(e0.x);
        float m0 = het ? e0.z : e0.y;
        float4 v0 = *(const float4*)&gather[(size_t)sr0 * gld + 4 * lane];
        ax = fmaf(m0, v0.x, ax);
        ay = fmaf(m0, v0.y, ay);
        az = fmaf(m0, v0.z, az);
        aw = fmaf(m0, v0.w, aw);
    }
    ax += bx;
    ay += by;
    az += bz;
    aw += bw;

    float inv = 1.f / d;
    float ox = fmaf(ax, inv, a.x);
    float oy = fmaf(ay, inv, a.y);
    float oz = fmaf(az, inv, a.z);
    float ow = fmaf(aw, inv, a.w);
    if (hom_b) {
        const float* bb = het ? het_b : hom_b;
        int bi = 4 * lane - (het ? 64 : 0);
        ox = fmaxf(ox + bb[bi + 0], 0.f);
        oy = fmaxf(oy + bb[bi + 1], 0.f);
        oz = fmaxf(oz + bb[bi + 2], 0.f);
        ow = fmaxf(ow + bb[bi + 3], 0.f);
    }
    *(float4*)&out[(size_t)gw * FDIM + 4 * lane] = make_float4(ox, oy, oz, ow);
}

// ---------------- readout: cat(max_pool, mean_pool) per graph ----------------
__global__ void readout_kernel(const float* __restrict__ h, int accumulate) {
    int g = blockIdx.x;
    int c = threadIdx.x;  // 128 threads = 2H features
    int s = g_gptr[g], e = g_gptr[g + 1];
    float mx = -INFINITY, sm = 0.f;
    for (int n = s; n < e; n++) {
        float v = h[(size_t)n * FDIM + c];
        mx = fmaxf(mx, v);
        sm += v;
    }
    float cnt = fmaxf((float)(e - s), 1.f);
    float mo = (e > s) ? mx : 0.f;
    float ao = sm / cnt;
    if (accumulate) {
        g_r[g * 256 + c] += mo;
        g_r[g * 256 + 128 + c] += ao;
    } else {
        g_r[g * 256 + c] = mo;
        g_r[g * 256 + 128 + c] = ao;
    }
}

// ---------------- MLP head + log_softmax ----------------
__global__ void mlp_kernel(const float* __restrict__ l1W, const float* __restrict__ l1b,
                           const float* __restrict__ l2W, const float* __restrict__ l2b,
                           const float* __restrict__ l3W, const float* __restrict__ l3b,
                           float* __restrict__ out) {
    int g = blockIdx.x;
    int t = threadIdx.x;  // 128 threads
    __shared__ float rs[256];
    __shared__ float z1[128];
    __shared__ float z2[64];
    __shared__ float lg[10];
    rs[t] = g_r[g * 256 + t];
    rs[t + 128] = g_r[g * 256 + 128 + t];
    __syncthreads();
    float acc = l1b[t];
#pragma unroll 8
    for (int k = 0; k < 256; k++) acc = fmaf(rs[k], l1W[k * 128 + t], acc);
    z1[t] = fmaxf(acc, 0.f);
    __syncthreads();
    if (t < 64) {
        float a = l2b[t];
#pragma unroll 8
        for (int k = 0; k < 128; k++) a = fmaf(z1[k], l2W[k * 64 + t], a);
        z2[t] = fmaxf(a, 0.f);
    }
    __syncthreads();
    if (t < 10) {
        float a = l3b[t];
#pragma unroll 8
        for (int k = 0; k < 64; k++) a = fmaf(z2[k], l3W[k * 10 + t], a);
        lg[t] = a;
    }
    __syncthreads();
    if (t == 0) {
        float mx = lg[0];
        for (int i = 1; i < CC; i++) mx = fmaxf(mx, lg[i]);
        float se = 0.f;
        for (int i = 0; i < CC; i++) se += expf(lg[i] - mx);
        float lse = mx + logf(se);
        for (int i = 0; i < CC; i++) out[g * CC + i] = lg[i] - lse;
    }
}

// ---------------- driver ----------------
extern "C" void kernel_launch(void* const* d_in, const int* in_sizes, int n_in,
                              void* d_out, int out_size) {
    const float* x       = (const float*)d_in[0];
    const int*   ei      = (const int*)d_in[1];
    const int*   batch   = (const int*)d_in[2];
    const float* hom_m   = (const float*)d_in[3];
    const float* het_m   = (const float*)d_in[4];
    const float* hom_W   = (const float*)d_in[5];
    const float* hom_b   = (const float*)d_in[6];
    const float* het_W   = (const float*)d_in[7];
    const float* het_b   = (const float*)d_in[8];
    const float* l1W     = (const float*)d_in[9];
    const float* l1b     = (const float*)d_in[10];
    const float* l2W     = (const float*)d_in[11];
    const float* l2b     = (const float*)d_in[12];
    const float* l3W     = (const float*)d_in[13];
    const float* l3b     = (const float*)d_in[14];
    float* out = (float*)d_out;
    (void)in_sizes; (void)n_in; (void)out_size;

    float *T_p, *h_p, *u_p;
    unsigned* Wbf_p;
    cudaGetSymbolAddress((void**)&T_p, g_T);
    cudaGetSymbolAddress((void**)&h_p, g_h);
    cudaGetSymbolAddress((void**)&u_p, g_u);
    cudaGetSymbolAddress((void**)&Wbf_p, g_Wbf);

    cudaFuncSetAttribute(gemm_bf16_kernel, cudaFuncAttributeMaxDynamicSharedMemorySize,
                         SM_WORDS * 4);

    const int aggBlocks = (NN * 32 + 255) / 256;
    const int mTiles = (NN + MTILE - 1) / MTILE;

    // launches 1-3: zero/count/pack; launch 4 = layer-0 GEMM (profiler window)
    init_zero_kernel<<<(NN + 255) / 256, 256>>>();
    count_kernel<<<(EE + 255) / 256, 256>>>(ei, hom_m, het_m);
    packWbf_kernel<<<(LL * 3 * 128 * 64 + 255) / 256, 256>>>(hom_W, het_W);
    gemm_bf16_kernel<<<mTiles, 256, SM_WORDS * 4>>>(x, Wbf_p, T_p);

    // CSR build (independent of the layer-0 GEMM)
    blkscan_kernel<<<(NN + 255) / 256, 256>>>();
    blkoff_kernel<<<1, 256>>>((NN + 255) / 256);
    finalize_scan_kernel<<<(NN + 255) / 256, 256>>>();
    gptr_kernel<<<(NN + 255) / 256, 256>>>(batch);
    scatter_kernel<<<(EE + 255) / 256, 256>>>(ei, hom_m, het_m);

    for (int l = 0; l < LL; l++) {
        if (l > 0)
            gemm_bf16_kernel<<<mTiles, 256, SM_WORDS * 4>>>(h_p, Wbf_p + (size_t)l * 3 * 2 * 8192, T_p);

        // hop1 (both views fused): u = A*(h W2) + (h W1)
        agg2_kernel<<<aggBlocks, 256>>>(T_p, TCOLS,
                                        T_p, TCOLS, 128,
                                        nullptr, nullptr,
                                        u_p);
        // hop2 (both views fused): h = relu( A*u + (h W0) + b )
        agg2_kernel<<<aggBlocks, 256>>>(u_p, FDIM,
                                        T_p, TCOLS, 256,
                                        hom_b + l * HDIM, het_b + l * HDIM,
                                        h_p);

        if (l >= 1) readout_kernel<<<GG, FDIM>>>(h_p, (l == 1) ? 0 : 1);
    }

    mlp_kernel<<<GG, 128>>>(l1W, l1b, l2W, l2b, l3W, l3b, out);
}

// round 13
// speedup vs baseline: 1.0796x; 1.0796x over previous
#include <cuda_runtime.h>
#include <cuda_bf16.h>
#include <math.h>
#include <stdint.h>

// Problem constants
#define NN   50000
#define EE   800000
#define FDIM 128
#define HDIM 64
#define LL   3
#define GG   256
#define CC   10
#define TCOLS 384   // 3 n-blocks of 128: [W2(hom|het) | W1(hom|het) | W0(hom|het)]

// ---------------- scratch (__device__ globals; no allocation allowed) ----------------
__device__ float g_T[(size_t)NN * TCOLS];     // per-layer GEMM output [N,384]
__device__ float g_h[(size_t)NN * FDIM];      // node features [N,128] (hom|het)
__device__ float g_u[(size_t)NN * FDIM];      // hop scratch [N,128] (hom|het)
// pre-split bf16 B images: [L][3 nblocks][2 planes][n=128][k=64 words]  (32KB per plane)
__device__ unsigned g_Wbf[LL * 3 * 2 * 8192];

__device__ int    g_cnt[NN];
__device__ int    g_fill[NN];
__device__ int    g_rowptr[NN + 1];
__device__ int    g_blk[256];
__device__ int    g_blkoff[256];
__device__ int    g_csr_src[EE];
__device__ float2 g_csr_mask[EE];             // (hom, het)
__device__ float  g_deg_hom[NN];
__device__ float  g_deg_het[NN];
__device__ int    g_gptr[GG + 1];
__device__ float  g_r[GG * 4 * HDIM];         // readout accumulator [G,256]

// ---------------- CSR build ----------------
__global__ void init_zero_kernel() {
    int i = blockIdx.x * blockDim.x + threadIdx.x;
    if (i < NN) {
        g_cnt[i] = 0;
        g_deg_hom[i] = 0.f;
        g_deg_het[i] = 0.f;
    }
}

__global__ void count_kernel(const int* __restrict__ ei,
                             const float* __restrict__ hm,
                             const float* __restrict__ tm) {
    int e = blockIdx.x * blockDim.x + threadIdx.x;
    if (e >= EE) return;
    int d = ei[EE + e];             // dst row of edge_index
    atomicAdd(&g_cnt[d], 1);
    atomicAdd(&g_deg_hom[d], hm[e]);
    atomicAdd(&g_deg_het[d], tm[e]);
}

// parallel exclusive scan of g_cnt -> g_rowptr/g_fill (3 kernels)
__global__ void blkscan_kernel() {   // grid 196, block 256
    __shared__ int s[256];
    int t = threadIdx.x;
    int i = blockIdx.x * 256 + t;
    int v = (i < NN) ? g_cnt[i] : 0;
    s[t] = v;
    __syncthreads();
#pragma unroll
    for (int off = 1; off < 256; off <<= 1) {
        int x = (t >= off) ? s[t - off] : 0;
        __syncthreads();
        s[t] += x;
        __syncthreads();
    }
    if (i < NN) g_rowptr[i] = s[t] - v;      // exclusive within block
    if (t == 255) g_blk[blockIdx.x] = s[255];
}

__global__ void blkoff_kernel(int nblk) {    // 1 block 256
    __shared__ int s[256];
    int t = threadIdx.x;
    int v = (t < nblk) ? g_blk[t] : 0;
    s[t] = v;
    __syncthreads();
#pragma unroll
    for (int off = 1; off < 256; off <<= 1) {
        int x = (t >= off) ? s[t - off] : 0;
        __syncthreads();
        s[t] += x;
        __syncthreads();
    }
    g_blkoff[t] = s[t] - v;                  // exclusive
}

__global__ void finalize_scan_kernel() {     // grid 196, block 256
    int i = blockIdx.x * blockDim.x + threadIdx.x;
    if (i < NN) {
        int r = g_rowptr[i] + g_blkoff[i >> 8];
        g_rowptr[i] = r;
        g_fill[i] = r;
    }
    if (i == 0) g_rowptr[NN] = EE;
}

__global__ void scatter_kernel(const int* __restrict__ ei,
                               const float* __restrict__ hm,
                               const float* __restrict__ tm) {
    int e = blockIdx.x * blockDim.x + threadIdx.x;
    if (e >= EE) return;
    int d = ei[EE + e];
    int p = atomicAdd(&g_fill[d], 1);
    g_csr_src[p] = ei[e];
    g_csr_mask[p] = make_float2(hm[e], tm[e]);
}

__global__ void gptr_kernel(const int* __restrict__ batch) {
    int n = blockIdx.x * blockDim.x + threadIdx.x;
    if (n >= NN) return;
    int b = batch[n];
    int prev = (n == 0) ? -1 : batch[n - 1];
    for (int g = prev + 1; g <= b; ++g) g_gptr[g] = n;
    if (n == NN - 1) {
        for (int g = b + 1; g <= GG; ++g) g_gptr[g] = NN;
    }
}

// ---------------- bf16 split ----------------
__device__ __forceinline__ void bf_split(float x, unsigned short& h, unsigned short& l) {
    __nv_bfloat16 hb = __float2bfloat16(x);
    float hf = __bfloat162float(hb);
    __nv_bfloat16 lb = __float2bfloat16(x - hf);
    h = __bfloat16_as_ushort(hb);
    l = __bfloat16_as_ushort(lb);
}

// pack all layers' weights: B[n][k] = W_l[hop j][k][col], split hi/lo planes.
// n-block t covers T cols t*128..t*128+127 -> hop j = 2 - t; view = (n>=64)
__global__ void packWbf_kernel(const float* __restrict__ homW,
                               const float* __restrict__ hetW) {
    int idx = blockIdx.x * blockDim.x + threadIdx.x;
    if (idx >= LL * 3 * 128 * 64) return;
    int kp = idx & 63;
    int n = (idx >> 6) & 127;
    int t = (idx >> 13) % 3;
    int l = idx / (3 * 128 * 64);
    int j = 2 - t;
    int v = (n >> 6) & 1;
    int cc = n & 63;
    const float* Ws = v ? hetW : homW;
    int k0 = 2 * kp;
    float f0 = Ws[((size_t)(l * 3 + j) * FDIM + k0) * HDIM + cc];
    float f1 = Ws[((size_t)(l * 3 + j) * FDIM + k0 + 1) * HDIM + cc];
    unsigned short h0, l0, h1, l1;
    bf_split(f0, h0, l0);
    bf_split(f1, h1, l1);
    unsigned* baseH = &g_Wbf[((size_t)(l * 3 + t) * 2 + 0) * 8192];
    unsigned* baseL = &g_Wbf[((size_t)(l * 3 + t) * 2 + 1) * 8192];
    baseH[n * 64 + kp] = (unsigned)h0 | ((unsigned)h1 << 16);
    baseL[n * 64 + kp] = (unsigned)l0 | ((unsigned)l1 << 16);
}

// ---------------- 3-pass bf16 mma.sync GEMM (v6): single B buffer, 3 CTAs/SM ----------------
// M tile 64, grid 782, 256 threads (8 warps). smem 69.6KB -> 3 CTAs/SM.
// B streamed in 6 chunks of 64 n-cols into ONE buffer; load exposure is covered
// by the other two CTAs on the SM (cross-CTA phase interleave).
#define MTILE 64
#define WPAD 68                            // words per row (stride 17x16B, odd -> conflict-free)
#define SM_AHI 0
#define SM_ALO (MTILE * WPAD)              // 4352
#define SM_B   (2 * MTILE * WPAD)          // 8704
#define BUFW   (2 * 64 * WPAD)             // 8704 words (hi+lo planes of 64 n-rows)
#define SM_WORDS (SM_B + BUFW)             // 17408 words = 69632 B

#define MMA_BF16(d, a0, a1, a2, a3, b0, b1)                                     \
    asm volatile(                                                               \
        "mma.sync.aligned.m16n8k16.row.col.f32.bf16.bf16.f32 "                  \
        "{%0,%1,%2,%3}, {%4,%5,%6,%7}, {%8,%9}, {%0,%1,%2,%3};"                 \
        : "+f"(d[0]), "+f"(d[1]), "+f"(d[2]), "+f"(d[3])                        \
        : "r"(a0), "r"(a1), "r"(a2), "r"(a3), "r"(b0), "r"(b1));

#define CP_ASYNC16(dst_u32, src_ptr)                                            \
    asm volatile("cp.async.cg.shared.global [%0], [%1], 16;"                    \
                 :: "r"(dst_u32), "l"(src_ptr) : "memory")
#define CP_COMMIT() asm volatile("cp.async.commit_group;" ::: "memory")
#define CP_WAIT0()  asm volatile("cp.async.wait_group 0;" ::: "memory")

__device__ __forceinline__ uint32_t smem_u32(const void* p) {
    uint32_t a;
    asm("{ .reg .u64 t; cvta.to.shared.u64 t, %1; cvt.u32.u64 %0, t; }" : "=r"(a) : "l"(p));
    return a;
}
__device__ __forceinline__ void ldsm_x4(unsigned& r0, unsigned& r1, unsigned& r2, unsigned& r3,
                                        uint32_t addr) {
    asm volatile("ldmatrix.sync.aligned.m8n8.x4.shared.b16 {%0,%1,%2,%3}, [%4];"
                 : "=r"(r0), "=r"(r1), "=r"(r2), "=r"(r3) : "r"(addr));
}

__global__ __launch_bounds__(256, 3) void gemm_bf16_kernel(const float* __restrict__ A,
                                                           const unsigned* __restrict__ Wb,
                                                           float* __restrict__ C) {
    extern __shared__ unsigned sm[];
    const uint32_t sbase = smem_u32(sm);
    const int tid = threadIdx.x;
    const int lane = tid & 31;
    const int wid = tid >> 5;
    const int g = lane >> 2;
    const int tg = lane & 3;
    const int warpRow = (wid & 1) * 32;        // 2 m-warps
    const int warpCol = (wid >> 1) * 16;       // 4 n-warps x 16 cols (within 64-col chunk)
    const int mBase = blockIdx.x * MTILE;

    // prefetch chunk c into the single B buffer (8 cp.async.16B per thread)
    auto prefetch = [&](int c) {
        int t = c >> 1, half = c & 1;
#pragma unroll
        for (int j = 0; j < 8; j++) {
            int task = tid + j * 256;              // 0..2047
            int plane = task >> 10;                // 0..1
            int rem = task & 1023;
            int r = rem >> 4;                      // 0..63
            int q = rem & 15;                      // 16B unit within row
            uint32_t dstw = SM_B + plane * (64 * WPAD) + r * WPAD + q * 4;
            const unsigned* src = Wb + (size_t)(t * 2 + plane) * 8192 + (half * 64 + r) * 64 + q * 4;
            CP_ASYNC16(sbase + dstw * 4, src);
        }
    };

    prefetch(0);
    CP_COMMIT();

    // ---- convert A tile [64 x 128] f32 -> bf16 hi/lo planes (overlaps prefetch) ----
    for (int it = tid; it < MTILE * 32; it += 256) {
        int row = it >> 5;
        int c4 = it & 31;
        int grow = mBase + row;
        float4 v = make_float4(0.f, 0.f, 0.f, 0.f);
        if (grow < NN) v = *(const float4*)&A[(size_t)grow * FDIM + 4 * c4];
        unsigned short hx, lx, hy, ly, hz, lz, hw, lw;
        bf_split(v.x, hx, lx);
        bf_split(v.y, hy, ly);
        bf_split(v.z, hz, lz);
        bf_split(v.w, hw, lw);
        int w0 = row * WPAD + 2 * c4;
        sm[SM_AHI + w0]     = (unsigned)hx | ((unsigned)hy << 16);
        sm[SM_AHI + w0 + 1] = (unsigned)hz | ((unsigned)hw << 16);
        sm[SM_ALO + w0]     = (unsigned)lx | ((unsigned)ly << 16);
        sm[SM_ALO + w0 + 1] = (unsigned)lz | ((unsigned)lw << 16);
    }

    const int aRow = (lane & 7) + ((lane >> 3) & 1) * 8;
    const int aWordSel = ((lane >> 4) & 1) * 4;
    const int bRowIdx = ((lane >> 4) & 1) * 8 + (lane & 7);
    const int bWordSel = ((lane >> 3) & 1) * 4;

    const uint32_t bH = sbase + SM_B * 4;
    const uint32_t bL = bH + (64 * WPAD) * 4;

    for (int c = 0; c < 6; c++) {
        const int t = c >> 1, half = c & 1;
        CP_WAIT0();
        __syncthreads();

        float acc[2][2][4];
#pragma unroll
        for (int mi = 0; mi < 2; mi++)
#pragma unroll
            for (int ni = 0; ni < 2; ni++)
#pragma unroll
                for (int r = 0; r < 4; r++) acc[mi][ni][r] = 0.f;

#pragma unroll
        for (int ks = 0; ks < 8; ks++) {
            unsigned ah[2][4], al[2][4];
#pragma unroll
            for (int mi = 0; mi < 2; mi++) {
                uint32_t off = (uint32_t)((warpRow + mi * 16 + aRow) * WPAD + 8 * ks + aWordSel) * 4;
                ldsm_x4(ah[mi][0], ah[mi][1], ah[mi][2], ah[mi][3],
                        sbase + SM_AHI * 4 + off);
                ldsm_x4(al[mi][0], al[mi][1], al[mi][2], al[mi][3],
                        sbase + SM_ALO * 4 + off);
            }
            unsigned bh[2][2], bl[2][2];
            {
                uint32_t off = (uint32_t)((warpCol + bRowIdx) * WPAD + 8 * ks + bWordSel) * 4;
                ldsm_x4(bh[0][0], bh[0][1], bh[1][0], bh[1][1], bH + off);
                ldsm_x4(bl[0][0], bl[0][1], bl[1][0], bl[1][1], bL + off);
            }
#pragma unroll
            for (int ni = 0; ni < 2; ni++)
#pragma unroll
                for (int mi = 0; mi < 2; mi++)
                    MMA_BF16(acc[mi][ni], ah[mi][0], ah[mi][1], ah[mi][2], ah[mi][3],
                             bh[ni][0], bh[ni][1]);
#pragma unroll
            for (int ni = 0; ni < 2; ni++)
#pragma unroll
                for (int mi = 0; mi < 2; mi++)
                    MMA_BF16(acc[mi][ni], al[mi][0], al[mi][1], al[mi][2], al[mi][3],
                             bh[ni][0], bh[ni][1]);
#pragma unroll
            for (int ni = 0; ni < 2; ni++)
#pragma unroll
                for (int mi = 0; mi < 2; mi++)
                    MMA_BF16(acc[mi][ni], ah[mi][0], ah[mi][1], ah[mi][2], ah[mi][3],
                             bl[ni][0], bl[ni][1]);
        }

        // ---- epilogue for this chunk ----
#pragma unroll
        for (int mi = 0; mi < 2; mi++) {
            int gr0 = mBase + warpRow + mi * 16 + g;
            int gr1 = gr0 + 8;
#pragma unroll
            for (int ni = 0; ni < 2; ni++) {
                int gc = t * 128 + half * 64 + warpCol + ni * 8 + 2 * tg;
                if (gr0 < NN)
                    *(float2*)&C[(size_t)gr0 * TCOLS + gc] = make_float2(acc[mi][ni][0], acc[mi][ni][1]);
                if (gr1 < NN)
                    *(float2*)&C[(size_t)gr1 * TCOLS + gc] = make_float2(acc[mi][ni][2], acc[mi][ni][3]);
            }
        }
        __syncthreads();          // all warps done reading the B buffer
        if (c + 1 < 6) {
            prefetch(c + 1);
            CP_COMMIT();
        }
    }
}

// ---------------- fused two-view aggregation (v1, round-10 proven): one warp per node ----------------
__global__ void agg2_kernel(const float* __restrict__ gather, int gld,
                            const float* __restrict__ add, int ald, int acol,
                            const float* __restrict__ hom_b,  // non-null => relu(.+bias)
                            const float* __restrict__ het_b,
                            float* __restrict__ out) {
    int gw = (blockIdx.x * blockDim.x + threadIdx.x) >> 5;
    int lane = threadIdx.x & 31;
    if (gw >= NN) return;
    const bool het = lane >= 16;
    int s = g_rowptr[gw];
    int e = g_rowptr[gw + 1];
    float ax = 0.f, ay = 0.f, az = 0.f, aw = 0.f;
    for (int i = s; i < e; i++) {
        int sr = g_csr_src[i];
        float2 mm = g_csr_mask[i];
        float m = het ? mm.y : mm.x;
        float4 v = *(const float4*)&gather[(size_t)sr * gld + 4 * lane];
        ax = fmaf(m, v.x, ax);
        ay = fmaf(m, v.y, ay);
        az = fmaf(m, v.z, az);
        aw = fmaf(m, v.w, aw);
    }
    float d = fmaxf(het ? g_deg_het[gw] : g_deg_hom[gw], 1.f);
    float inv = 1.f / d;
    float4 a = *(const float4*)&add[(size_t)gw * ald + acol + 4 * lane];
    float ox = fmaf(ax, inv, a.x);
    float oy = fmaf(ay, inv, a.y);
    float oz = fmaf(az, inv, a.z);
    float ow = fmaf(aw, inv, a.w);
    if (hom_b) {
        const float* bb = het ? het_b : hom_b;
        int bi = 4 * lane - (het ? 64 : 0);
        ox = fmaxf(ox + bb[bi + 0], 0.f);
        oy = fmaxf(oy + bb[bi + 1], 0.f);
        oz = fmaxf(oz + bb[bi + 2], 0.f);
        ow = fmaxf(ow + bb[bi + 3], 0.f);
    }
    *(float4*)&out[(size_t)gw * FDIM + 4 * lane] = make_float4(ox, oy, oz, ow);
}

// ---------------- readout: cat(max_pool, mean_pool) per graph ----------------
__global__ void readout_kernel(const float* __restrict__ h, int accumulate) {
    int g = blockIdx.x;
    int c = threadIdx.x;  // 128 threads = 2H features
    int s = g_gptr[g], e = g_gptr[g + 1];
    float mx = -INFINITY, sm = 0.f;
    for (int n = s; n < e; n++) {
        float v = h[(size_t)n * FDIM + c];
        mx = fmaxf(mx, v);
        sm += v;
    }
    float cnt = fmaxf((float)(e - s), 1.f);
    float mo = (e > s) ? mx : 0.f;
    float ao = sm / cnt;
    if (accumulate) {
        g_r[g * 256 + c] += mo;
        g_r[g * 256 + 128 + c] += ao;
    } else {
        g_r[g * 256 + c] = mo;
        g_r[g * 256 + 128 + c] = ao;
    }
}

// ---------------- MLP head + log_softmax ----------------
__global__ void mlp_kernel(const float* __restrict__ l1W, const float* __restrict__ l1b,
                           const float* __restrict__ l2W, const float* __restrict__ l2b,
                           const float* __restrict__ l3W, const float* __restrict__ l3b,
                           float* __restrict__ out) {
    int g = blockIdx.x;
    int t = threadIdx.x;  // 128 threads
    __shared__ float rs[256];
    __shared__ float z1[128];
    __shared__ float z2[64];
    __shared__ float lg[10];
    rs[t] = g_r[g * 256 + t];
    rs[t + 128] = g_r[g * 256 + 128 + t];
    __syncthreads();
    float acc = l1b[t];
#pragma unroll 8
    for (int k = 0; k < 256; k++) acc = fmaf(rs[k], l1W[k * 128 + t], acc);
    z1[t] = fmaxf(acc, 0.f);
    __syncthreads();
    if (t < 64) {
        float a = l2b[t];
#pragma unroll 8
        for (int k = 0; k < 128; k++) a = fmaf(z1[k], l2W[k * 64 + t], a);
        z2[t] = fmaxf(a, 0.f);
    }
    __syncthreads();
    if (t < 10) {
        float a = l3b[t];
#pragma unroll 8
        for (int k = 0; k < 64; k++) a = fmaf(z2[k], l3W[k * 10 + t], a);
        lg[t] = a;
    }
    __syncthreads();
    if (t == 0) {
        float mx = lg[0];
        for (int i = 1; i < CC; i++) mx = fmaxf(mx, lg[i]);
        float se = 0.f;
        for (int i = 0; i < CC; i++) se += expf(lg[i] - mx);
        float lse = mx + logf(se);
        for (int i = 0; i < CC; i++) out[g * CC + i] = lg[i] - lse;
    }
}

// ---------------- driver ----------------
extern "C" void kernel_launch(void* const* d_in, const int* in_sizes, int n_in,
                              void* d_out, int out_size) {
    const float* x       = (const float*)d_in[0];
    const int*   ei      = (const int*)d_in[1];
    const int*   batch   = (const int*)d_in[2];
    const float* hom_m   = (const float*)d_in[3];
    const float* het_m   = (const float*)d_in[4];
    const float* hom_W   = (const float*)d_in[5];
    const float* hom_b   = (const float*)d_in[6];
    const float* het_W   = (const float*)d_in[7];
    const float* het_b   = (const float*)d_in[8];
    const float* l1W     = (const float*)d_in[9];
    const float* l1b     = (const float*)d_in[10];
    const float* l2W     = (const float*)d_in[11];
    const float* l2b     = (const float*)d_in[12];
    const float* l3W     = (const float*)d_in[13];
    const float* l3b     = (const float*)d_in[14];
    float* out = (float*)d_out;
    (void)in_sizes; (void)n_in; (void)out_size;

    float *T_p, *h_p, *u_p;
    unsigned* Wbf_p;
    cudaGetSymbolAddress((void**)&T_p, g_T);
    cudaGetSymbolAddress((void**)&h_p, g_h);
    cudaGetSymbolAddress((void**)&u_p, g_u);
    cudaGetSymbolAddress((void**)&Wbf_p, g_Wbf);

    cudaFuncSetAttribute(gemm_bf16_kernel, cudaFuncAttributeMaxDynamicSharedMemorySize,
                         SM_WORDS * 4);

    const int aggBlocks = (NN * 32 + 255) / 256;
    const int mTiles = (NN + MTILE - 1) / MTILE;

    // launches 1-3: zero/count/pack; launch 4 = layer-0 GEMM (profiler window)
    init_zero_kernel<<<(NN + 255) / 256, 256>>>();
    count_kernel<<<(EE + 255) / 256, 256>>>(ei, hom_m, het_m);
    packWbf_kernel<<<(LL * 3 * 128 * 64 + 255) / 256, 256>>>(hom_W, het_W);
    gemm_bf16_kernel<<<mTiles, 256, SM_WORDS * 4>>>(x, Wbf_p, T_p);

    // CSR build (independent of the layer-0 GEMM)
    blkscan_kernel<<<(NN + 255) / 256, 256>>>();
    blkoff_kernel<<<1, 256>>>((NN + 255) / 256);
    finalize_scan_kernel<<<(NN + 255) / 256, 256>>>();
    gptr_kernel<<<(NN + 255) / 256, 256>>>(batch);
    scatter_kernel<<<(EE + 255) / 256, 256>>>(ei, hom_m, het_m);

    for (int l = 0; l < LL; l++) {
        if (l > 0)
            gemm_bf16_kernel<<<mTiles, 256, SM_WORDS * 4>>>(h_p, Wbf_p + (size_t)l * 3 * 2 * 8192, T_p);

        // hop1 (both views fused): u = A*(h W2) + (h W1)
        agg2_kernel<<<aggBlocks, 256>>>(T_p, TCOLS,
                                        T_p, TCOLS, 128,
                                        nullptr, nullptr,
                                        u_p);
        // hop2 (both views fused): h = relu( A*u + (h W0) + b )
        agg2_kernel<<<aggBlocks, 256>>>(u_p, FDIM,
                                        T_p, TCOLS, 256,
                                        hom_b + l * HDIM, het_b + l * HDIM,
                                        h_p);

        if (l >= 1) readout_kernel<<<GG, FDIM>>>(h_p, (l == 1) ? 0 : 1);
    }

    mlp_kernel<<<GG, 128>>>(l1W, l1b, l2W, l2b, l3W, l3b, out);
}

// round 14
// speedup vs baseline: 1.0912x; 1.0107x over previous
#include <cuda_runtime.h>
#include <cuda_bf16.h>
#include <math.h>
#include <stdint.h>

// Problem constants
#define NN   50000
#define EE   800000
#define FDIM 128
#define HDIM 64
#define LL   3
#define GG   256
#define CC   10
#define TCOLS 384   // 3 n-blocks of 128: [W2(hom|het) | W1(hom|het) | W0(hom|het)]

// ---------------- scratch (__device__ globals; no allocation allowed) ----------------
__device__ float g_T[(size_t)NN * TCOLS];     // per-layer GEMM output [N,384]
__device__ float g_h[(size_t)NN * FDIM];      // node features [N,128] (hom|het)
__device__ float g_u[(size_t)NN * FDIM];      // hop scratch [N,128] (hom|het)
// pre-split bf16 B images: [L][3 nblocks][2 planes][n=128][k=64 words]  (32KB per plane)
__device__ unsigned g_Wbf[LL * 3 * 2 * 8192];

__device__ int    g_cnt[NN];
__device__ int    g_fill[NN];
__device__ int    g_rowptr[NN + 1];
__device__ int    g_blk[256];
__device__ int    g_csr_src[EE];
__device__ float2 g_csr_mask[EE];             // (hom, het)
__device__ int    g_gptr[GG + 1];
__device__ float  g_r[GG * 4 * HDIM];         // readout accumulator [G,256]

// ---------------- CSR build ----------------
__global__ void init_zero_kernel() {
    int i = blockIdx.x * blockDim.x + threadIdx.x;
    if (i < NN) g_cnt[i] = 0;
}

__global__ void count_kernel(const int* __restrict__ ei) {
    int e = blockIdx.x * blockDim.x + threadIdx.x;
    if (e >= EE) return;
    atomicAdd(&g_cnt[ei[EE + e]], 1);
}

// parallel exclusive scan of g_cnt -> g_rowptr/g_fill (2 kernels)
__global__ void blkscan_kernel() {   // grid 196, block 256
    __shared__ int s[256];
    int t = threadIdx.x;
    int i = blockIdx.x * 256 + t;
    int v = (i < NN) ? g_cnt[i] : 0;
    s[t] = v;
    __syncthreads();
#pragma unroll
    for (int off = 1; off < 256; off <<= 1) {
        int x = (t >= off) ? s[t - off] : 0;
        __syncthreads();
        s[t] += x;
        __syncthreads();
    }
    if (i < NN) g_rowptr[i] = s[t] - v;      // exclusive within block
    if (t == 255) g_blk[blockIdx.x] = s[255];
}

// each block reduces its own prefix of g_blk (196 entries) -> no separate blkoff pass
__global__ void finalize_scan_kernel() {     // grid 196, block 256
    __shared__ int s[256];
    int t = threadIdx.x;
    s[t] = (t < (int)blockIdx.x && t < 196) ? g_blk[t] : 0;
    __syncthreads();
#pragma unroll
    for (int off = 128; off > 0; off >>= 1) {
        if (t < off) s[t] += s[t + off];
        __syncthreads();
    }
    int base = s[0];
    int i = blockIdx.x * 256 + t;
    if (i < NN) {
        int r = g_rowptr[i] + base;
        g_rowptr[i] = r;
        g_fill[i] = r;
    }
    if (i == 0) g_rowptr[NN] = EE;
}

__global__ void scatter_kernel(const int* __restrict__ ei,
                               const float* __restrict__ hm,
                               const float* __restrict__ tm) {
    int e = blockIdx.x * blockDim.x + threadIdx.x;
    if (e >= EE) return;
    int d = ei[EE + e];
    int p = atomicAdd(&g_fill[d], 1);
    g_csr_src[p] = ei[e];
    g_csr_mask[p] = make_float2(hm[e], tm[e]);
}

__global__ void gptr_kernel(const int* __restrict__ batch) {
    int n = blockIdx.x * blockDim.x + threadIdx.x;
    if (n >= NN) return;
    int b = batch[n];
    int prev = (n == 0) ? -1 : batch[n - 1];
    for (int g = prev + 1; g <= b; ++g) g_gptr[g] = n;
    if (n == NN - 1) {
        for (int g = b + 1; g <= GG; ++g) g_gptr[g] = NN;
    }
}

// ---------------- bf16 split ----------------
__device__ __forceinline__ void bf_split(float x, unsigned short& h, unsigned short& l) {
    __nv_bfloat16 hb = __float2bfloat16(x);
    float hf = __bfloat162float(hb);
    __nv_bfloat16 lb = __float2bfloat16(x - hf);
    h = __bfloat16_as_ushort(hb);
    l = __bfloat16_as_ushort(lb);
}

// pack all layers' weights: B[n][k] = W_l[hop j][k][col], split hi/lo planes.
// n-block t covers T cols t*128..t*128+127 -> hop j = 2 - t; view = (n>=64)
__global__ void packWbf_kernel(const float* __restrict__ homW,
                               const float* __restrict__ hetW) {
    int idx = blockIdx.x * blockDim.x + threadIdx.x;
    if (idx >= LL * 3 * 128 * 64) return;
    int kp = idx & 63;
    int n = (idx >> 6) & 127;
    int t = (idx >> 13) % 3;
    int l = idx / (3 * 128 * 64);
    int j = 2 - t;
    int v = (n >> 6) & 1;
    int cc = n & 63;
    const float* Ws = v ? hetW : homW;
    int k0 = 2 * kp;
    float f0 = Ws[((size_t)(l * 3 + j) * FDIM + k0) * HDIM + cc];
    float f1 = Ws[((size_t)(l * 3 + j) * FDIM + k0 + 1) * HDIM + cc];
    unsigned short h0, l0, h1, l1;
    bf_split(f0, h0, l0);
    bf_split(f1, h1, l1);
    unsigned* baseH = &g_Wbf[((size_t)(l * 3 + t) * 2 + 0) * 8192];
    unsigned* baseL = &g_Wbf[((size_t)(l * 3 + t) * 2 + 1) * 8192];
    baseH[n * 64 + kp] = (unsigned)h0 | ((unsigned)h1 << 16);
    baseL[n * 64 + kp] = (unsigned)l0 | ((unsigned)l1 << 16);
}

// ---------------- 3-pass bf16 mma.sync GEMM (v6): single B buffer, 3 CTAs/SM ----------------
#define MTILE 64
#define WPAD 68                            // words per row (stride 17x16B, odd -> conflict-free)
#define SM_AHI 0
#define SM_ALO (MTILE * WPAD)              // 4352
#define SM_B   (2 * MTILE * WPAD)          // 8704
#define BUFW   (2 * 64 * WPAD)             // 8704 words (hi+lo planes of 64 n-rows)
#define SM_WORDS (SM_B + BUFW)             // 17408 words = 69632 B

#define MMA_BF16(d, a0, a1, a2, a3, b0, b1)                                     \
    asm volatile(                                                               \
        "mma.sync.aligned.m16n8k16.row.col.f32.bf16.bf16.f32 "                  \
        "{%0,%1,%2,%3}, {%4,%5,%6,%7}, {%8,%9}, {%0,%1,%2,%3};"                 \
        : "+f"(d[0]), "+f"(d[1]), "+f"(d[2]), "+f"(d[3])                        \
        : "r"(a0), "r"(a1), "r"(a2), "r"(a3), "r"(b0), "r"(b1));

#define CP_ASYNC16(dst_u32, src_ptr)                                            \
    asm volatile("cp.async.cg.shared.global [%0], [%1], 16;"                    \
                 :: "r"(dst_u32), "l"(src_ptr) : "memory")
#define CP_COMMIT() asm volatile("cp.async.commit_group;" ::: "memory")
#define CP_WAIT0()  asm volatile("cp.async.wait_group 0;" ::: "memory")

__device__ __forceinline__ uint32_t smem_u32(const void* p) {
    uint32_t a;
    asm("{ .reg .u64 t; cvta.to.shared.u64 t, %1; cvt.u32.u64 %0, t; }" : "=r"(a) : "l"(p));
    return a;
}
__device__ __forceinline__ void ldsm_x4(unsigned& r0, unsigned& r1, unsigned& r2, unsigned& r3,
                                        uint32_t addr) {
    asm volatile("ldmatrix.sync.aligned.m8n8.x4.shared.b16 {%0,%1,%2,%3}, [%4];"
                 : "=r"(r0), "=r"(r1), "=r"(r2), "=r"(r3) : "r"(addr));
}

__global__ __launch_bounds__(256, 3) void gemm_bf16_kernel(const float* __restrict__ A,
                                                           const unsigned* __restrict__ Wb,
                                                           float* __restrict__ C) {
    extern __shared__ unsigned sm[];
    const uint32_t sbase = smem_u32(sm);
    const int tid = threadIdx.x;
    const int lane = tid & 31;
    const int wid = tid >> 5;
    const int g = lane >> 2;
    const int tg = lane & 3;
    const int warpRow = (wid & 1) * 32;        // 2 m-warps
    const int warpCol = (wid >> 1) * 16;       // 4 n-warps x 16 cols (within 64-col chunk)
    const int mBase = blockIdx.x * MTILE;

    auto prefetch = [&](int c) {
        int t = c >> 1, half = c & 1;
#pragma unroll
        for (int j = 0; j < 8; j++) {
            int task = tid + j * 256;              // 0..2047
            int plane = task >> 10;                // 0..1
            int rem = task & 1023;
            int r = rem >> 4;                      // 0..63
            int q = rem & 15;                      // 16B unit within row
            uint32_t dstw = SM_B + plane * (64 * WPAD) + r * WPAD + q * 4;
            const unsigned* src = Wb + (size_t)(t * 2 + plane) * 8192 + (half * 64 + r) * 64 + q * 4;
            CP_ASYNC16(sbase + dstw * 4, src);
        }
    };

    prefetch(0);
    CP_COMMIT();

    // ---- convert A tile [64 x 128] f32 -> bf16 hi/lo planes (overlaps prefetch) ----
    for (int it = tid; it < MTILE * 32; it += 256) {
        int row = it >> 5;
        int c4 = it & 31;
        int grow = mBase + row;
        float4 v = make_float4(0.f, 0.f, 0.f, 0.f);
        if (grow < NN) v = *(const float4*)&A[(size_t)grow * FDIM + 4 * c4];
        unsigned short hx, lx, hy, ly, hz, lz, hw, lw;
        bf_split(v.x, hx, lx);
        bf_split(v.y, hy, ly);
        bf_split(v.z, hz, lz);
        bf_split(v.w, hw, lw);
        int w0 = row * WPAD + 2 * c4;
        sm[SM_AHI + w0]     = (unsigned)hx | ((unsigned)hy << 16);
        sm[SM_AHI + w0 + 1] = (unsigned)hz | ((unsigned)hw << 16);
        sm[SM_ALO + w0]     = (unsigned)lx | ((unsigned)ly << 16);
        sm[SM_ALO + w0 + 1] = (unsigned)lz | ((unsigned)lw << 16);
    }

    const int aRow = (lane & 7) + ((lane >> 3) & 1) * 8;
    const int aWordSel = ((lane >> 4) & 1) * 4;
    const int bRowIdx = ((lane >> 4) & 1) * 8 + (lane & 7);
    const int bWordSel = ((lane >> 3) & 1) * 4;

    const uint32_t bH = sbase + SM_B * 4;
    const uint32_t bL = bH + (64 * WPAD) * 4;

    for (int c = 0; c < 6; c++) {
        const int t = c >> 1, half = c & 1;
        CP_WAIT0();
        __syncthreads();

        float acc[2][2][4];
#pragma unroll
        for (int mi = 0; mi < 2; mi++)
#pragma unroll
            for (int ni = 0; ni < 2; ni++)
#pragma unroll
                for (int r = 0; r < 4; r++) acc[mi][ni][r] = 0.f;

#pragma unroll
        for (int ks = 0; ks < 8; ks++) {
            unsigned ah[2][4], al[2][4];
#pragma unroll
            for (int mi = 0; mi < 2; mi++) {
                uint32_t off = (uint32_t)((warpRow + mi * 16 + aRow) * WPAD + 8 * ks + aWordSel) * 4;
                ldsm_x4(ah[mi][0], ah[mi][1], ah[mi][2], ah[mi][3],
                        sbase + SM_AHI * 4 + off);
                ldsm_x4(al[mi][0], al[mi][1], al[mi][2], al[mi][3],
                        sbase + SM_ALO * 4 + off);
            }
            unsigned bh[2][2], bl[2][2];
            {
                uint32_t off = (uint32_t)((warpCol + bRowIdx) * WPAD + 8 * ks + bWordSel) * 4;
                ldsm_x4(bh[0][0], bh[0][1], bh[1][0], bh[1][1], bH + off);
                ldsm_x4(bl[0][0], bl[0][1], bl[1][0], bl[1][1], bL + off);
            }
#pragma unroll
            for (int ni = 0; ni < 2; ni++)
#pragma unroll
                for (int mi = 0; mi < 2; mi++)
                    MMA_BF16(acc[mi][ni], ah[mi][0], ah[mi][1], ah[mi][2], ah[mi][3],
                             bh[ni][0], bh[ni][1]);
#pragma unroll
            for (int ni = 0; ni < 2; ni++)
#pragma unroll
                for (int mi = 0; mi < 2; mi++)
                    MMA_BF16(acc[mi][ni], al[mi][0], al[mi][1], al[mi][2], al[mi][3],
                             bh[ni][0], bh[ni][1]);
#pragma unroll
            for (int ni = 0; ni < 2; ni++)
#pragma unroll
                for (int mi = 0; mi < 2; mi++)
                    MMA_BF16(acc[mi][ni], ah[mi][0], ah[mi][1], ah[mi][2], ah[mi][3],
                             bl[ni][0], bl[ni][1]);
        }

        // ---- epilogue for this chunk ----
#pragma unroll
        for (int mi = 0; mi < 2; mi++) {
            int gr0 = mBase + warpRow + mi * 16 + g;
            int gr1 = gr0 + 8;
#pragma unroll
            for (int ni = 0; ni < 2; ni++) {
                int gc = t * 128 + half * 64 + warpCol + ni * 8 + 2 * tg;
                if (gr0 < NN)
                    *(float2*)&C[(size_t)gr0 * TCOLS + gc] = make_float2(acc[mi][ni][0], acc[mi][ni][1]);
                if (gr1 < NN)
                    *(float2*)&C[(size_t)gr1 * TCOLS + gc] = make_float2(acc[mi][ni][2], acc[mi][ni][3]);
            }
        }
        __syncthreads();          // all warps done reading the B buffer
        if (c + 1 < 6) {
            prefetch(c + 1);
            CP_COMMIT();
        }
    }
}

// ---------------- fused two-view aggregation: one warp per node; deg computed in-loop ----------------
__global__ void agg2_kernel(const float* __restrict__ gather, int gld,
                            const float* __restrict__ add, int ald, int acol,
                            const float* __restrict__ hom_b,  // non-null => relu(.+bias)
                            const float* __restrict__ het_b,
                            float* __restrict__ out) {
    int gw = (blockIdx.x * blockDim.x + threadIdx.x) >> 5;
    int lane = threadIdx.x & 31;
    if (gw >= NN) return;
    const bool het = lane >= 16;
    int s = g_rowptr[gw];
    int e = g_rowptr[gw + 1];
    float ax = 0.f, ay = 0.f, az = 0.f, aw = 0.f;
    float dm = 0.f;                                // deg accumulator (= sum of masks)
    for (int i = s; i < e; i++) {
        int sr = g_csr_src[i];
        float2 mm = g_csr_mask[i];
        float m = het ? mm.y : mm.x;
        float4 v = *(const float4*)&gather[(size_t)sr * gld + 4 * lane];
        dm += m;
        ax = fmaf(m, v.x, ax);
        ay = fmaf(m, v.y, ay);
        az = fmaf(m, v.z, az);
        aw = fmaf(m, v.w, aw);
    }
    float d = fmaxf(dm, 1.f);
    float inv = 1.f / d;
    float4 a = *(const float4*)&add[(size_t)gw * ald + acol + 4 * lane];
    float ox = fmaf(ax, inv, a.x);
    float oy = fmaf(ay, inv, a.y);
    float oz = fmaf(az, inv, a.z);
    float ow = fmaf(aw, inv, a.w);
    if (hom_b) {
        const float* bb = het ? het_b : hom_b;
        int bi = 4 * lane - (het ? 64 : 0);
        ox = fmaxf(ox + bb[bi + 0], 0.f);
        oy = fmaxf(oy + bb[bi + 1], 0.f);
        oz = fmaxf(oz + bb[bi + 2], 0.f);
        ow = fmaxf(ow + bb[bi + 3], 0.f);
    }
    *(float4*)&out[(size_t)gw * FDIM + 4 * lane] = make_float4(ox, oy, oz, ow);
}

// ---------------- readout: cat(max_pool, mean_pool) per graph ----------------
__global__ void readout_kernel(const float* __restrict__ h, int accumulate) {
    int g = blockIdx.x;
    int c = threadIdx.x;  // 128 threads = 2H features
    int s = g_gptr[g], e = g_gptr[g + 1];
    float mx = -INFINITY, sm = 0.f;
    for (int n = s; n < e; n++) {
        float v = h[(size_t)n * FDIM + c];
        mx = fmaxf(mx, v);
        sm += v;
    }
    float cnt = fmaxf((float)(e - s), 1.f);
    float mo = (e > s) ? mx : 0.f;
    float ao = sm / cnt;
    if (accumulate) {
        g_r[g * 256 + c] += mo;
        g_r[g * 256 + 128 + c] += ao;
    } else {
        g_r[g * 256 + c] = mo;
        g_r[g * 256 + 128 + c] = ao;
    }
}

// ---------------- MLP head + log_softmax ----------------
__global__ void mlp_kernel(const float* __restrict__ l1W, const float* __restrict__ l1b,
                           const float* __restrict__ l2W, const float* __restrict__ l2b,
                           const float* __restrict__ l3W, const float* __restrict__ l3b,
                           float* __restrict__ out) {
    int g = blockIdx.x;
    int t = threadIdx.x;  // 128 threads
    __shared__ float rs[256];
    __shared__ float z1[128];
    __shared__ float z2[64];
    __shared__ float lg[10];
    rs[t] = g_r[g * 256 + t];
    rs[t + 128] = g_r[g * 256 + 128 + t];
    __syncthreads();
    float acc = l1b[t];
#pragma unroll 8
    for (int k = 0; k < 256; k++) acc = fmaf(rs[k], l1W[k * 128 + t], acc);
    z1[t] = fmaxf(acc, 0.f);
    __syncthreads();
    if (t < 64) {
        float a = l2b[t];
#pragma unroll 8
        for (int k = 0; k < 128; k++) a = fmaf(z1[k], l2W[k * 64 + t], a);
        z2[t] = fmaxf(a, 0.f);
    }
    __syncthreads();
    if (t < 10) {
        float a = l3b[t];
#pragma unroll 8
        for (int k = 0; k < 64; k++) a = fmaf(z2[k], l3W[k * 10 + t], a);
        lg[t] = a;
    }
    __syncthreads();
    if (t == 0) {
        float mx = lg[0];
        for (int i = 1; i < CC; i++) mx = fmaxf(mx, lg[i]);
        float se = 0.f;
        for (int i = 0; i < CC; i++) se += expf(lg[i] - mx);
        float lse = mx + logf(se);
        for (int i = 0; i < CC; i++) out[g * CC + i] = lg[i] - lse;
    }
}

// ---------------- driver ----------------
extern "C" void kernel_launch(void* const* d_in, const int* in_sizes, int n_in,
                              void* d_out, int out_size) {
    const float* x       = (const float*)d_in[0];
    const int*   ei      = (const int*)d_in[1];
    const int*   batch   = (const int*)d_in[2];
    const float* hom_m   = (const float*)d_in[3];
    const float* het_m   = (const float*)d_in[4];
    const float* hom_W   = (const float*)d_in[5];
    const float* hom_b   = (const float*)d_in[6];
    const float* het_W   = (const float*)d_in[7];
    const float* het_b   = (const float*)d_in[8];
    const float* l1W     = (const float*)d_in[9];
    const float* l1b     = (const float*)d_in[10];
    const float* l2W     = (const float*)d_in[11];
    const float* l2b     = (const float*)d_in[12];
    const float* l3W     = (const float*)d_in[13];
    const float* l3b     = (const float*)d_in[14];
    float* out = (float*)d_out;
    (void)in_sizes; (void)n_in; (void)out_size;

    float *T_p, *h_p, *u_p;
    unsigned* Wbf_p;
    cudaGetSymbolAddress((void**)&T_p, g_T);
    cudaGetSymbolAddress((void**)&h_p, g_h);
    cudaGetSymbolAddress((void**)&u_p, g_u);
    cudaGetSymbolAddress((void**)&Wbf_p, g_Wbf);

    cudaFuncSetAttribute(gemm_bf16_kernel, cudaFuncAttributeMaxDynamicSharedMemorySize,
                         SM_WORDS * 4);

    const int aggBlocks = (NN * 32 + 255) / 256;
    const int mTiles = (NN + MTILE - 1) / MTILE;

    // launches 1-3: zero/count/pack; launch 4 = layer-0 GEMM (profiler window)
    init_zero_kernel<<<(NN + 255) / 256, 256>>>();
    count_kernel<<<(EE + 255) / 256, 256>>>(ei);
    packWbf_kernel<<<(LL * 3 * 128 * 64 + 255) / 256, 256>>>(hom_W, het_W);
    gemm_bf16_kernel<<<mTiles, 256, SM_WORDS * 4>>>(x, Wbf_p, T_p);

    // CSR build (independent of the layer-0 GEMM)
    blkscan_kernel<<<(NN + 255) / 256, 256>>>();
    finalize_scan_kernel<<<(NN + 255) / 256, 256>>>();
    gptr_kernel<<<(NN + 255) / 256, 256>>>(batch);
    scatter_kernel<<<(EE + 255) / 256, 256>>>(ei, hom_m, het_m);

    for (int l = 0; l < LL; l++) {
        if (l > 0)
            gemm_bf16_kernel<<<mTiles, 256, SM_WORDS * 4>>>(h_p, Wbf_p + (size_t)l * 3 * 2 * 8192, T_p);

        // hop1 (both views fused): u = A*(h W2) + (h W1)
        agg2_kernel<<<aggBlocks, 256>>>(T_p, TCOLS,
                                        T_p, TCOLS, 128,
                                        nullptr, nullptr,
                                        u_p);
        // hop2 (both views fused): h = relu( A*u + (h W0) + b )
        agg2_kernel<<<aggBlocks, 256>>>(u_p, FDIM,
                                        T_p, TCOLS, 256,
                                        hom_b + l * HDIM, het_b + l * HDIM,
                                        h_p);

        if (l >= 1) readout_kernel<<<GG, FDIM>>>(h_p, (l == 1) ? 0 : 1);
    }

    mlp_kernel<<<GG, 128>>>(l1W, l1b, l2W, l2b, l3W, l3b, out);
}

// round 15
// speedup vs baseline: 1.1250x; 1.0310x over previous
#include <cuda_runtime.h>
#include <cuda_bf16.h>
#include <math.h>
#include <stdint.h>

// Problem constants
#define NN   50000
#define EE   800000
#define FDIM 128
#define HDIM 64
#define LL   3
#define GG   256
#define CC   10
#define TCOLS 384   // 3 n-blocks of 128: [W2(hom|het) | W1(hom|het) | W0(hom|het)]

// ---------------- scratch (__device__ globals; no allocation allowed) ----------------
__device__ float g_T[(size_t)NN * TCOLS];     // per-layer GEMM output [N,384]
__device__ float g_h[(size_t)NN * FDIM];      // node features [N,128] (hom|het)
__device__ float g_u[(size_t)NN * FDIM];      // hop scratch [N,128] (hom|het)
// pre-split bf16 B images: [L][3 nblocks][2 planes][n=128][k=64 words]  (32KB per plane)
__device__ unsigned g_Wbf[LL * 3 * 2 * 8192];

__device__ int    g_cnt[NN];
__device__ int    g_fill[NN];
__device__ int    g_rowptr[NN + 1];
__device__ int    g_blk[256];
__device__ int    g_csr_src[EE];
__device__ float2 g_csr_mask[EE];             // (hom, het)
__device__ int    g_gptr[GG + 1];
__device__ float  g_r[GG * 4 * HDIM];         // readout accumulator [G,256]

// ---------------- CSR build ----------------
__global__ void init_zero_kernel() {
    int i = blockIdx.x * blockDim.x + threadIdx.x;
    if (i < NN) g_cnt[i] = 0;
}

__global__ void count_kernel(const int* __restrict__ ei) {
    int e = blockIdx.x * blockDim.x + threadIdx.x;
    if (e >= EE) return;
    atomicAdd(&g_cnt[ei[EE + e]], 1);
}

// parallel exclusive scan of g_cnt -> g_rowptr/g_fill (2 kernels)
__global__ void blkscan_kernel() {   // grid 196, block 256
    __shared__ int s[256];
    int t = threadIdx.x;
    int i = blockIdx.x * 256 + t;
    int v = (i < NN) ? g_cnt[i] : 0;
    s[t] = v;
    __syncthreads();
#pragma unroll
    for (int off = 1; off < 256; off <<= 1) {
        int x = (t >= off) ? s[t - off] : 0;
        __syncthreads();
        s[t] += x;
        __syncthreads();
    }
    if (i < NN) g_rowptr[i] = s[t] - v;      // exclusive within block
    if (t == 255) g_blk[blockIdx.x] = s[255];
}

// each block reduces its own prefix of g_blk (196 entries) -> no separate blkoff pass
__global__ void finalize_scan_kernel() {     // grid 196, block 256
    __shared__ int s[256];
    int t = threadIdx.x;
    s[t] = (t < (int)blockIdx.x && t < 196) ? g_blk[t] : 0;
    __syncthreads();
#pragma unroll
    for (int off = 128; off > 0; off >>= 1) {
        if (t < off) s[t] += s[t + off];
        __syncthreads();
    }
    int base = s[0];
    int i = blockIdx.x * 256 + t;
    if (i < NN) {
        int r = g_rowptr[i] + base;
        g_rowptr[i] = r;
        g_fill[i] = r;
    }
    if (i == 0) g_rowptr[NN] = EE;
}

__global__ void scatter_kernel(const int* __restrict__ ei,
                               const float* __restrict__ hm,
                               const float* __restrict__ tm) {
    int e = blockIdx.x * blockDim.x + threadIdx.x;
    if (e >= EE) return;
    int d = ei[EE + e];
    int p = atomicAdd(&g_fill[d], 1);
    g_csr_src[p] = ei[e];
    g_csr_mask[p] = make_float2(hm[e], tm[e]);
}

__global__ void gptr_kernel(const int* __restrict__ batch) {
    int n = blockIdx.x * blockDim.x + threadIdx.x;
    if (n >= NN) return;
    int b = batch[n];
    int prev = (n == 0) ? -1 : batch[n - 1];
    for (int g = prev + 1; g <= b; ++g) g_gptr[g] = n;
    if (n == NN - 1) {
        for (int g = b + 1; g <= GG; ++g) g_gptr[g] = NN;
    }
}

// ---------------- bf16 split ----------------
__device__ __forceinline__ void bf_split(float x, unsigned short& h, unsigned short& l) {
    __nv_bfloat16 hb = __float2bfloat16(x);
    float hf = __bfloat162float(hb);
    __nv_bfloat16 lb = __float2bfloat16(x - hf);
    h = __bfloat16_as_ushort(hb);
    l = __bfloat16_as_ushort(lb);
}

// pack all layers' weights: B[n][k] = W_l[hop j][k][col], split hi/lo planes.
// n-block t covers T cols t*128..t*128+127 -> hop j = 2 - t; view = (n>=64)
__global__ void packWbf_kernel(const float* __restrict__ homW,
                               const float* __restrict__ hetW) {
    int idx = blockIdx.x * blockDim.x + threadIdx.x;
    if (idx >= LL * 3 * 128 * 64) return;
    int kp = idx & 63;
    int n = (idx >> 6) & 127;
    int t = (idx >> 13) % 3;
    int l = idx / (3 * 128 * 64);
    int j = 2 - t;
    int v = (n >> 6) & 1;
    int cc = n & 63;
    const float* Ws = v ? hetW : homW;
    int k0 = 2 * kp;
    float f0 = Ws[((size_t)(l * 3 + j) * FDIM + k0) * HDIM + cc];
    float f1 = Ws[((size_t)(l * 3 + j) * FDIM + k0 + 1) * HDIM + cc];
    unsigned short h0, l0, h1, l1;
    bf_split(f0, h0, l0);
    bf_split(f1, h1, l1);
    unsigned* baseH = &g_Wbf[((size_t)(l * 3 + t) * 2 + 0) * 8192];
    unsigned* baseL = &g_Wbf[((size_t)(l * 3 + t) * 2 + 1) * 8192];
    baseH[n * 64 + kp] = (unsigned)h0 | ((unsigned)h1 << 16);
    baseL[n * 64 + kp] = (unsigned)l0 | ((unsigned)l1 << 16);
}

// ---------------- 3-pass bf16 mma.sync GEMM (v6): single B buffer, 3 CTAs/SM ----------------
#define MTILE 64
#define WPAD 68                            // words per row (stride 17x16B, odd -> conflict-free)
#define SM_AHI 0
#define SM_ALO (MTILE * WPAD)              // 4352
#define SM_B   (2 * MTILE * WPAD)          // 8704
#define BUFW   (2 * 64 * WPAD)             // 8704 words (hi+lo planes of 64 n-rows)
#define SM_WORDS (SM_B + BUFW)             // 17408 words = 69632 B

#define MMA_BF16(d, a0, a1, a2, a3, b0, b1)                                     \
    asm volatile(                                                               \
        "mma.sync.aligned.m16n8k16.row.col.f32.bf16.bf16.f32 "                  \
        "{%0,%1,%2,%3}, {%4,%5,%6,%7}, {%8,%9}, {%0,%1,%2,%3};"                 \
        : "+f"(d[0]), "+f"(d[1]), "+f"(d[2]), "+f"(d[3])                        \
        : "r"(a0), "r"(a1), "r"(a2), "r"(a3), "r"(b0), "r"(b1));

#define CP_ASYNC16(dst_u32, src_ptr)                                            \
    asm volatile("cp.async.cg.shared.global [%0], [%1], 16;"                    \
                 :: "r"(dst_u32), "l"(src_ptr) : "memory")
#define CP_COMMIT() asm volatile("cp.async.commit_group;" ::: "memory")
#define CP_WAIT0()  asm volatile("cp.async.wait_group 0;" ::: "memory")

__device__ __forceinline__ uint32_t smem_u32(const void* p) {
    uint32_t a;
    asm("{ .reg .u64 t; cvta.to.shared.u64 t, %1; cvt.u32.u64 %0, t; }" : "=r"(a) : "l"(p));
    return a;
}
__device__ __forceinline__ void ldsm_x4(unsigned& r0, unsigned& r1, unsigned& r2, unsigned& r3,
                                        uint32_t addr) {
    asm volatile("ldmatrix.sync.aligned.m8n8.x4.shared.b16 {%0,%1,%2,%3}, [%4];"
                 : "=r"(r0), "=r"(r1), "=r"(r2), "=r"(r3) : "r"(addr));
}

__global__ __launch_bounds__(256, 3) void gemm_bf16_kernel(const float* __restrict__ A,
                                                           const unsigned* __restrict__ Wb,
                                                           float* __restrict__ C) {
    extern __shared__ unsigned sm[];
    const uint32_t sbase = smem_u32(sm);
    const int tid = threadIdx.x;
    const int lane = tid & 31;
    const int wid = tid >> 5;
    const int g = lane >> 2;
    const int tg = lane & 3;
    const int warpRow = (wid & 1) * 32;        // 2 m-warps
    const int warpCol = (wid >> 1) * 16;       // 4 n-warps x 16 cols (within 64-col chunk)
    const int mBase = blockIdx.x * MTILE;

    auto prefetch = [&](int c) {
        int t = c >> 1, half = c & 1;
#pragma unroll
        for (int j = 0; j < 8; j++) {
            int task = tid + j * 256;              // 0..2047
            int plane = task >> 10;                // 0..1
            int rem = task & 1023;
            int r = rem >> 4;                      // 0..63
            int q = rem & 15;                      // 16B unit within row
            uint32_t dstw = SM_B + plane * (64 * WPAD) + r * WPAD + q * 4;
            const unsigned* src = Wb + (size_t)(t * 2 + plane) * 8192 + (half * 64 + r) * 64 + q * 4;
            CP_ASYNC16(sbase + dstw * 4, src);
        }
    };

    prefetch(0);
    CP_COMMIT();

    // ---- convert A tile [64 x 128] f32 -> bf16 hi/lo planes (overlaps prefetch) ----
    for (int it = tid; it < MTILE * 32; it += 256) {
        int row = it >> 5;
        int c4 = it & 31;
        int grow = mBase + row;
        float4 v = make_float4(0.f, 0.f, 0.f, 0.f);
        if (grow < NN) v = *(const float4*)&A[(size_t)grow * FDIM + 4 * c4];
        unsigned short hx, lx, hy, ly, hz, lz, hw, lw;
        bf_split(v.x, hx, lx);
        bf_split(v.y, hy, ly);
        bf_split(v.z, hz, lz);
        bf_split(v.w, hw, lw);
        int w0 = row * WPAD + 2 * c4;
        sm[SM_AHI + w0]     = (unsigned)hx | ((unsigned)hy << 16);
        sm[SM_AHI + w0 + 1] = (unsigned)hz | ((unsigned)hw << 16);
        sm[SM_ALO + w0]     = (unsigned)lx | ((unsigned)ly << 16);
        sm[SM_ALO + w0 + 1] = (unsigned)lz | ((unsigned)lw << 16);
    }

    const int aRow = (lane & 7) + ((lane >> 3) & 1) * 8;
    const int aWordSel = ((lane >> 4) & 1) * 4;
    const int bRowIdx = ((lane >> 4) & 1) * 8 + (lane & 7);
    const int bWordSel = ((lane >> 3) & 1) * 4;

    const uint32_t bH = sbase + SM_B * 4;
    const uint32_t bL = bH + (64 * WPAD) * 4;

    for (int c = 0; c < 6; c++) {
        const int t = c >> 1, half = c & 1;
        CP_WAIT0();
        __syncthreads();

        float acc[2][2][4];
#pragma unroll
        for (int mi = 0; mi < 2; mi++)
#pragma unroll
            for (int ni = 0; ni < 2; ni++)
#pragma unroll
                for (int r = 0; r < 4; r++) acc[mi][ni][r] = 0.f;

#pragma unroll
        for (int ks = 0; ks < 8; ks++) {
            unsigned ah[2][4], al[2][4];
#pragma unroll
            for (int mi = 0; mi < 2; mi++) {
                uint32_t off = (uint32_t)((warpRow + mi * 16 + aRow) * WPAD + 8 * ks + aWordSel) * 4;
                ldsm_x4(ah[mi][0], ah[mi][1], ah[mi][2], ah[mi][3],
                        sbase + SM_AHI * 4 + off);
                ldsm_x4(al[mi][0], al[mi][1], al[mi][2], al[mi][3],
                        sbase + SM_ALO * 4 + off);
            }
            unsigned bh[2][2], bl[2][2];
            {
                uint32_t off = (uint32_t)((warpCol + bRowIdx) * WPAD + 8 * ks + bWordSel) * 4;
                ldsm_x4(bh[0][0], bh[0][1], bh[1][0], bh[1][1], bH + off);
                ldsm_x4(bl[0][0], bl[0][1], bl[1][0], bl[1][1], bL + off);
            }
#pragma unroll
            for (int ni = 0; ni < 2; ni++)
#pragma unroll
                for (int mi = 0; mi < 2; mi++)
                    MMA_BF16(acc[mi][ni], ah[mi][0], ah[mi][1], ah[mi][2], ah[mi][3],
                             bh[ni][0], bh[ni][1]);
#pragma unroll
            for (int ni = 0; ni < 2; ni++)
#pragma unroll
                for (int mi = 0; mi < 2; mi++)
                    MMA_BF16(acc[mi][ni], al[mi][0], al[mi][1], al[mi][2], al[mi][3],
                             bh[ni][0], bh[ni][1]);
#pragma unroll
            for (int ni = 0; ni < 2; ni++)
#pragma unroll
                for (int mi = 0; mi < 2; mi++)
                    MMA_BF16(acc[mi][ni], ah[mi][0], ah[mi][1], ah[mi][2], ah[mi][3],
                             bl[ni][0], bl[ni][1]);
        }

        // ---- epilogue for this chunk ----
#pragma unroll
        for (int mi = 0; mi < 2; mi++) {
            int gr0 = mBase + warpRow + mi * 16 + g;
            int gr1 = gr0 + 8;
#pragma unroll
            for (int ni = 0; ni < 2; ni++) {
                int gc = t * 128 + half * 64 + warpCol + ni * 8 + 2 * tg;
                if (gr0 < NN)
                    *(float2*)&C[(size_t)gr0 * TCOLS + gc] = make_float2(acc[mi][ni][0], acc[mi][ni][1]);
                if (gr1 < NN)
                    *(float2*)&C[(size_t)gr1 * TCOLS + gc] = make_float2(acc[mi][ni][2], acc[mi][ni][3]);
            }
        }
        __syncthreads();          // all warps done reading the B buffer
        if (c + 1 < 6) {
            prefetch(c + 1);
            CP_COMMIT();
        }
    }
}

// ---------------- fused two-view aggregation: one warp per node; deg computed in-loop ----------------
__global__ void agg2_kernel(const float* __restrict__ gather, int gld,
                            const float* __restrict__ add, int ald, int acol,
                            const float* __restrict__ hom_b,  // non-null => relu(.+bias)
                            const float* __restrict__ het_b,
                            float* __restrict__ out) {
    int gw = (blockIdx.x * blockDim.x + threadIdx.x) >> 5;
    int lane = threadIdx.x & 31;
    if (gw >= NN) return;
    const bool het = lane >= 16;
    int s = g_rowptr[gw];
    int e = g_rowptr[gw + 1];
    float ax = 0.f, ay = 0.f, az = 0.f, aw = 0.f;
    float dm = 0.f;                                // deg accumulator (= sum of masks)
    for (int i = s; i < e; i++) {
        int sr = g_csr_src[i];
        float2 mm = g_csr_mask[i];
        float m = het ? mm.y : mm.x;
        float4 v = *(const float4*)&gather[(size_t)sr * gld + 4 * lane];
        dm += m;
        ax = fmaf(m, v.x, ax);
        ay = fmaf(m, v.y, ay);
        az = fmaf(m, v.z, az);
        aw = fmaf(m, v.w, aw);
    }
    float d = fmaxf(dm, 1.f);
    float inv = 1.f / d;
    float4 a = *(const float4*)&add[(size_t)gw * ald + acol + 4 * lane];
    float ox = fmaf(ax, inv, a.x);
    float oy = fmaf(ay, inv, a.y);
    float oz = fmaf(az, inv, a.z);
    float ow = fmaf(aw, inv, a.w);
    if (hom_b) {
        const float* bb = het ? het_b : hom_b;
        int bi = 4 * lane - (het ? 64 : 0);
        ox = fmaxf(ox + bb[bi + 0], 0.f);
        oy = fmaxf(oy + bb[bi + 1], 0.f);
        oz = fmaxf(oz + bb[bi + 2], 0.f);
        ow = fmaxf(ow + bb[bi + 3], 0.f);
    }
    *(float4*)&out[(size_t)gw * FDIM + 4 * lane] = make_float4(ox, oy, oz, ow);
}

// ---------------- readout: cat(max_pool, mean_pool) per graph ----------------
__global__ void readout_kernel(const float* __restrict__ h, int accumulate) {
    int g = blockIdx.x;
    int c = threadIdx.x;  // 128 threads = 2H features
    int s = g_gptr[g], e = g_gptr[g + 1];
    float mx = -INFINITY, sm = 0.f;
    for (int n = s; n < e; n++) {
        float v = h[(size_t)n * FDIM + c];
        mx = fmaxf(mx, v);
        sm += v;
    }
    float cnt = fmaxf((float)(e - s), 1.f);
    float mo = (e > s) ? mx : 0.f;
    float ao = sm / cnt;
    if (accumulate) {
        g_r[g * 256 + c] += mo;
        g_r[g * 256 + 128 + c] += ao;
    } else {
        g_r[g * 256 + c] = mo;
        g_r[g * 256 + 128 + c] = ao;
    }
}

// ---------------- MLP head + log_softmax ----------------
__global__ void mlp_kernel(const float* __restrict__ l1W, const float* __restrict__ l1b,
                           const float* __restrict__ l2W, const float* __restrict__ l2b,
                           const float* __restrict__ l3W, const float* __restrict__ l3b,
                           float* __restrict__ out) {
    int g = blockIdx.x;
    int t = threadIdx.x;  // 128 threads
    __shared__ float rs[256];
    __shared__ float z1[128];
    __shared__ float z2[64];
    __shared__ float lg[10];
    rs[t] = g_r[g * 256 + t];
    rs[t + 128] = g_r[g * 256 + 128 + t];
    __syncthreads();
    float acc = l1b[t];
#pragma unroll 8
    for (int k = 0; k < 256; k++) acc = fmaf(rs[k], l1W[k * 128 + t], acc);
    z1[t] = fmaxf(acc, 0.f);
    __syncthreads();
    if (t < 64) {
        float a = l2b[t];
#pragma unroll 8
        for (int k = 0; k < 128; k++) a = fmaf(z1[k], l2W[k * 64 + t], a);
        z2[t] = fmaxf(a, 0.f);
    }
    __syncthreads();
    if (t < 10) {
        float a = l3b[t];
#pragma unroll 8
        for (int k = 0; k < 64; k++) a = fmaf(z2[k], l3W[k * 10 + t], a);
        lg[t] = a;
    }
    __syncthreads();
    if (t == 0) {
        float mx = lg[0];
        for (int i = 1; i < CC; i++) mx = fmaxf(mx, lg[i]);
        float se = 0.f;
        for (int i = 0; i < CC; i++) se += expf(lg[i] - mx);
        float lse = mx + logf(se);
        for (int i = 0; i < CC; i++) out[g * CC + i] = lg[i] - lse;
    }
}

// ---------------- driver ----------------
extern "C" void kernel_launch(void* const* d_in, const int* in_sizes, int n_in,
                              void* d_out, int out_size) {
    const float* x       = (const float*)d_in[0];
    const int*   ei      = (const int*)d_in[1];
    const int*   batch   = (const int*)d_in[2];
    const float* hom_m   = (const float*)d_in[3];
    const float* het_m   = (const float*)d_in[4];
    const float* hom_W   = (const float*)d_in[5];
    const float* hom_b   = (const float*)d_in[6];
    const float* het_W   = (const float*)d_in[7];
    const float* het_b   = (const float*)d_in[8];
    const float* l1W     = (const float*)d_in[9];
    const float* l1b     = (const float*)d_in[10];
    const float* l2W     = (const float*)d_in[11];
    const float* l2b     = (const float*)d_in[12];
    const float* l3W     = (const float*)d_in[13];
    const float* l3b     = (const float*)d_in[14];
    float* out = (float*)d_out;
    (void)in_sizes; (void)n_in; (void)out_size;

    float *T_p, *h_p, *u_p;
    unsigned* Wbf_p;
    cudaGetSymbolAddress((void**)&T_p, g_T);
    cudaGetSymbolAddress((void**)&h_p, g_h);
    cudaGetSymbolAddress((void**)&u_p, g_u);
    cudaGetSymbolAddress((void**)&Wbf_p, g_Wbf);

    cudaFuncSetAttribute(gemm_bf16_kernel, cudaFuncAttributeMaxDynamicSharedMemorySize,
                         SM_WORDS * 4);

    const int aggBlocks = (NN * 32 + 255) / 256;
    const int mTiles = (NN + MTILE - 1) / MTILE;

    // side stream + events for capture-fork parallelism.
    // Created fresh per call (host-side objects only; intentionally not destroyed
    // so capture-forked nodes stay valid -- no device memory involved).
    cudaStream_t s2;
    cudaStreamCreate(&s2);
    cudaEvent_t eFork, eCsr, eRoStart, eRoDone;
    cudaEventCreateWithFlags(&eFork, cudaEventDisableTiming);
    cudaEventCreateWithFlags(&eCsr, cudaEventDisableTiming);
    cudaEventCreateWithFlags(&eRoStart, cudaEventDisableTiming);
    cudaEventCreateWithFlags(&eRoDone, cudaEventDisableTiming);

    // ---- fork: CSR build on s2, concurrent with packW + layer-0 GEMM on main ----
    cudaEventRecord(eFork, 0);
    cudaStreamWaitEvent(s2, eFork, 0);
    init_zero_kernel<<<(NN + 255) / 256, 256, 0, s2>>>();
    count_kernel<<<(EE + 255) / 256, 256, 0, s2>>>(ei);
    blkscan_kernel<<<(NN + 255) / 256, 256, 0, s2>>>();
    finalize_scan_kernel<<<(NN + 255) / 256, 256, 0, s2>>>();
    gptr_kernel<<<(NN + 255) / 256, 256, 0, s2>>>(batch);
    scatter_kernel<<<(EE + 255) / 256, 256, 0, s2>>>(ei, hom_m, het_m);
    cudaEventRecord(eCsr, s2);

    packWbf_kernel<<<(LL * 3 * 128 * 64 + 255) / 256, 256>>>(hom_W, het_W);
    gemm_bf16_kernel<<<mTiles, 256, SM_WORDS * 4>>>(x, Wbf_p, T_p);

    // join: aggregation needs the CSR
    cudaStreamWaitEvent(0, eCsr, 0);

    for (int l = 0; l < LL; l++) {
        if (l > 0)
            gemm_bf16_kernel<<<mTiles, 256, SM_WORDS * 4>>>(h_p, Wbf_p + (size_t)l * 3 * 2 * 8192, T_p);

        // hop1 (both views fused): u = A*(h W2) + (h W1)
        agg2_kernel<<<aggBlocks, 256>>>(T_p, TCOLS,
                                        T_p, TCOLS, 128,
                                        nullptr, nullptr,
                                        u_p);

        // join readout(l=1) before hop2 of l=2 overwrites h
        if (l == 2) cudaStreamWaitEvent(0, eRoDone, 0);

        // hop2 (both views fused): h = relu( A*u + (h W0) + b )
        agg2_kernel<<<aggBlocks, 256>>>(u_p, FDIM,
                                        T_p, TCOLS, 256,
                                        hom_b + l * HDIM, het_b + l * HDIM,
                                        h_p);

        if (l == 1) {
            // fork readout(l=1) onto s2; it runs concurrent with layer-2 GEMM + hop1 agg
            cudaEventRecord(eRoStart, 0);
            cudaStreamWaitEvent(s2, eRoStart, 0);
            readout_kernel<<<GG, FDIM, 0, s2>>>(h_p, 0);
            cudaEventRecord(eRoDone, s2);
        } else if (l == 2) {
            readout_kernel<<<GG, FDIM>>>(h_p, 1);
        }
    }

    mlp_kernel<<<GG, 128>>>(l1W, l1b, l2W, l2b, l3W, l3b, out);
}